// round 1
// baseline (speedup 1.0000x reference)
#include <cuda_runtime.h>
#include <cstdint>

// MultiHashRouter on GB300/B200 (sm_100a-compatible source; compiled per target arch).
//
// Reference math collapses:
//   routing = XOR_{d=0..63} (dim_value[d] * (d+1))      (LAYER_ID=0, SALT=0)
//   expert_ids[h] = (routing & 63) ^ h  for h=0..3  -> always 4 distinct ids
//   => selected = [r&63, (r&63)^1], weights = 0.5, masks two 0.5 hits per row.
//
// One warp per token: coalesced float2 load of the 64 leading dims,
// butterfly XOR reduce, coalesced float2 mask-row store.

#define HIDDEN_DIM 1024
#define USED_DIMS  64
#define N_EXPERTS  64
#define K_ACTIVE   2

__device__ __forceinline__ uint32_t dim_weighted(float h, int d /*0-based*/) {
    // sign: -1 -> 3, +1 -> 1, 0 -> 0 (after &3)
    int s = (h > 0.0f) ? 1 : ((h < 0.0f) ? -1 : 0);
    int mag = (int)fminf(fabsf(h), 7.0f);           // == clip(int(abs(h)),0,7)
    int dv = ((s & 3) << 2) | (mag & 7);
    return (uint32_t)(dv * (d + 1));
}

__global__ __launch_bounds__(256, 8)
void multihash_router_kernel(const float* __restrict__ hs,
                             float* __restrict__ out_sel,    // [N,2] (ids as float) or null
                             float* __restrict__ out_w,      // [N,2] or null
                             float* __restrict__ out_mask,   // [N,64] or null
                             int n_tokens)
{
    const int warp_in_block = threadIdx.x >> 5;
    const int lane = threadIdx.x & 31;
    const int token = blockIdx.x * 8 + warp_in_block;
    if (token >= n_tokens) return;

    // ---- load 2 dims per lane (coalesced 256B per warp) ----
    const float2 hv = reinterpret_cast<const float2*>(hs + (size_t)token * HIDDEN_DIM)[lane];
    const int d0 = lane * 2;
    uint32_t r = dim_weighted(hv.x, d0) ^ dim_weighted(hv.y, d0 + 1);

    // ---- butterfly XOR reduce across the warp ----
    #pragma unroll
    for (int off = 16; off > 0; off >>= 1)
        r ^= __shfl_xor_sync(0xFFFFFFFFu, r, off);

    const uint32_t base = r & 63u;      // expert id for hash 0
    const uint32_t e0 = base;
    const uint32_t e1 = base ^ 1u;      // hash 1 id; always != e0

    // ---- selected experts + weights (lane 0, float2 stores) ----
    if (lane == 0) {
        if (out_sel)
            reinterpret_cast<float2*>(out_sel)[token] =
                make_float2((float)e0, (float)e1);
        if (out_w)
            reinterpret_cast<float2*>(out_w)[token] = make_float2(0.5f, 0.5f);
    }

    // ---- mask row: 64 floats, 2 per lane, coalesced ----
    if (out_mask) {
        const uint32_t c0 = (uint32_t)(lane * 2);
        const uint32_t c1 = c0 + 1u;
        float2 mv;
        mv.x = (c0 == e0 || c0 == e1) ? 0.5f : 0.0f;
        mv.y = (c1 == e0 || c1 == e1) ? 0.5f : 0.0f;
        reinterpret_cast<float2*>(out_mask)[token * (N_EXPERTS / 2) + lane] = mv;
    }
}

extern "C" void kernel_launch(void* const* d_in, const int* in_sizes, int n_in,
                              void* d_out, int out_size)
{
    const float* hs = (const float*)d_in[0];
    const int n_tokens = in_sizes[0] / HIDDEN_DIM;

    float* out = (float*)d_out;
    float* out_sel = nullptr;
    float* out_w = nullptr;
    float* out_mask = nullptr;

    const long long n = n_tokens;
    if ((long long)out_size == n * (K_ACTIVE + K_ACTIVE + N_EXPERTS)) {
        // concat layout: [selected (2N) | weights (2N) | masks (64N)]
        out_sel  = out;
        out_w    = out + 2 * n;
        out_mask = out + 4 * n;
    } else if ((long long)out_size == n * N_EXPERTS) {
        out_mask = out;                  // masks only
    } else if ((long long)out_size == n * K_ACTIVE) {
        out_sel = out;                   // selected only
    } else {
        // Unknown layout: best effort — treat as concat prefix.
        out_sel  = out;
        if ((long long)out_size >= 4 * n) out_w = out + 2 * n;
        if ((long long)out_size >= 4 * n + n * N_EXPERTS) out_mask = out + 4 * n;
    }

    const int warps_per_block = 8;
    const int blocks = (n_tokens + warps_per_block - 1) / warps_per_block;
    multihash_router_kernel<<<blocks, warps_per_block * 32>>>(
        hs, out_sel, out_w, out_mask, n_tokens);
}

// round 4
// speedup vs baseline: 1.2031x; 1.2031x over previous
#include <cuda_runtime.h>
#include <cstdint>

// MultiHashRouter — issue-bound optimization round (re-bench after infra failure).
//
// Math (LAYER_ID=0, SALT=0):
//   routing r = XOR_{d=0..63} dim_value[d]*(d+1)
//   expert_ids[h] = (r & 63) ^ h, h=0..3 -> always distinct
//   selected = [base, base^1], weights = 0.5
//   mask row: 0.5 at the aligned column pair {base&~1, base|1}.
//
// Layout: 2 tokens per warp. half=lane>>4 picks token, l=lane&15 picks the
// float4 chunk (dims 4l..4l+3). XOR butterfly over each 16-lane half.

#define HIDDEN_DIM 1024
#define N_EXPERTS  64
#define K_ACTIVE   2

__device__ __forceinline__ uint32_t dim_weighted(float h, int dplus1) {
    // sign code: +1 -> 1, -1 -> 3 (=-1&3), 0/-0 -> 0
    int s = (h > 0.0f) ? 1 : ((h < 0.0f) ? 3 : 0);
    int mag = (int)fminf(fabsf(h), 7.0f);     // == clip(int(|h|), 0, 7)
    return (uint32_t)(((s << 2) | mag) * dplus1);
}

__global__ __launch_bounds__(256, 8)
void multihash_router_kernel(const float4* __restrict__ hs4,
                             float2* __restrict__ out_sel,   // [N,2] or null
                             float2* __restrict__ out_w,     // [N,2] or null
                             float4* __restrict__ out_mask,  // [N,16] float4 or null
                             int n_tokens)
{
    const uint32_t lane = threadIdx.x & 31u;
    const uint32_t warp = threadIdx.x >> 5;
    const uint32_t half = lane >> 4;             // 0: token A, 1: token B
    const uint32_t l    = lane & 15u;            // float4 chunk within token
    const uint32_t token = (blockIdx.x * 8u + warp) * 2u + half;
    if (token >= (uint32_t)n_tokens) return;

    // ---- one LDG.128 per lane: dims 4l .. 4l+3 of this token ----
    const float4 hv = hs4[token * (HIDDEN_DIM / 4) + l];

    const int d1 = 4 * (int)l + 1;               // 1-based multiplier of first dim
    uint32_t r = dim_weighted(hv.x, d1)
               ^ dim_weighted(hv.y, d1 + 1)
               ^ dim_weighted(hv.z, d1 + 2)
               ^ dim_weighted(hv.w, d1 + 3);

    // ---- butterfly XOR reduce over each 16-lane half ----
    #pragma unroll
    for (int off = 8; off > 0; off >>= 1)
        r ^= __shfl_xor_sync(0xFFFFFFFFu, r, off);

    const uint32_t base = r & 63u;               // hash-0 expert; hash-1 is base^1

    // ---- mask row: lane owns cols 4l..4l+3; hit pair is {base&~1, base|1} ----
    float4 mv = make_float4(0.0f, 0.0f, 0.0f, 0.0f);
    if ((base >> 2) == l) {
        if (base & 2u) { mv.z = 0.5f; mv.w = 0.5f; }
        else           { mv.x = 0.5f; mv.y = 0.5f; }
    }
    if (out_mask)
        out_mask[token * (N_EXPERTS / 4) + l] = mv;

    // ---- selected experts + weights (lanes 0 and 16, one per token) ----
    if (l == 0) {
        if (out_sel)
            out_sel[token] = make_float2((float)base, (float)(base ^ 1u));
        if (out_w)
            out_w[token] = make_float2(0.5f, 0.5f);
    }
}

extern "C" void kernel_launch(void* const* d_in, const int* in_sizes, int n_in,
                              void* d_out, int out_size)
{
    const float4* hs4 = (const float4*)d_in[0];
    const int n_tokens = in_sizes[0] / HIDDEN_DIM;

    float* out = (float*)d_out;
    float2* out_sel = nullptr;
    float2* out_w = nullptr;
    float4* out_mask = nullptr;

    const long long n = n_tokens;
    if ((long long)out_size == n * (K_ACTIVE + K_ACTIVE + N_EXPERTS)) {
        // concat layout: [selected (2N) | weights (2N) | masks (64N)]
        out_sel  = (float2*)out;
        out_w    = (float2*)(out + 2 * n);
        out_mask = (float4*)(out + 4 * n);
    } else if ((long long)out_size == n * N_EXPERTS) {
        out_mask = (float4*)out;
    } else if ((long long)out_size == n * K_ACTIVE) {
        out_sel = (float2*)out;
    } else {
        out_sel = (float2*)out;
        if ((long long)out_size >= 4 * n) out_w = (float2*)(out + 2 * n);
        if ((long long)out_size >= 4 * n + n * N_EXPERTS)
            out_mask = (float4*)(out + 4 * n);
    }

    // 256 threads = 8 warps = 16 tokens per block
    const int blocks = (n_tokens + 15) / 16;
    multihash_router_kernel<<<blocks, 256>>>(hs4, out_sel, out_w, out_mask, n_tokens);
}

// round 7
// speedup vs baseline: 1.3899x; 1.1552x over previous
#include <cuda_runtime.h>
#include <cstdint>

// MultiHashRouter — latency/overhead-bound round.
// (Re-submit: prior two rounds were broker/container failures; removed the
//  large static __device__ scratch arrays as the only kernel-side suspect.)
//
// Math (LAYER_ID=0, SALT=0):
//   r = XOR_{d=0..63} dim_value[d]*(d+1);  expert_ids[h] = (r&63)^h (all distinct)
//   selected = [base, base^1], weights = 0.5
//   mask row: 0.5 at the aligned column pair {base&~1, base|1}.
//
// 4 tokens per warp: 8 lanes per token, each lane loads 2 float4 chunks
// (MLP=2), 3-step butterfly over 8 lanes, unconditional coalesced stores.
// Output layout (verified over two passing rounds):
//   [selected (2N) | weights (2N) | masks (64N)]  as float32.

#define HIDDEN_DIM 1024
#define N_EXPERTS  64
#define K_ACTIVE   2

__device__ __forceinline__ uint32_t dim_weighted(float h, uint32_t dplus1) {
    uint32_t u  = __float_as_uint(h);
    uint32_t au = u & 0x7fffffffu;                       // |h| bits; 0 iff h==±0
    uint32_t mag = (uint32_t)min((int)fabsf(h), 7);      // F2I(|h|) + IMNMX
    uint32_t code = ((u >> 28) & 8u) | 4u;               // 4 (pos) / 12 (neg)
    uint32_t dv = au ? (code | mag) : 0u;                // ±0 -> dim_value 0
    return dv * dplus1;
}

__global__ __launch_bounds__(128, 16)
void multihash_router_kernel(const float4* __restrict__ hs4,
                             float2* __restrict__ out_sel,   // [N]
                             float2* __restrict__ out_w,     // [N]
                             float4* __restrict__ out_mask,  // [N,16]
                             int n_tokens)
{
    const uint32_t lane = threadIdx.x & 31u;
    const uint32_t warp = threadIdx.x >> 5;
    const uint32_t tw   = lane >> 3;        // token within warp, 0..3
    const uint32_t j    = lane & 7u;        // chunk lane within token, 0..7
    const uint32_t token = (blockIdx.x * 4u + warp) * 4u + tw;
    if (token >= (uint32_t)n_tokens) return;

    // ---- two LDG.128 per lane, issued back-to-back (MLP=2) ----
    const float4* row = hs4 + token * (HIDDEN_DIM / 4);
    const float4 a = row[j];        // dims 4j .. 4j+3
    const float4 b = row[j + 8];    // dims 4j+32 .. 4j+35

    const uint32_t d1 = 4u * j + 1u;
    uint32_t r = dim_weighted(a.x, d1)       ^ dim_weighted(a.y, d1 + 1u)
               ^ dim_weighted(a.z, d1 + 2u)  ^ dim_weighted(a.w, d1 + 3u)
               ^ dim_weighted(b.x, d1 + 32u) ^ dim_weighted(b.y, d1 + 33u)
               ^ dim_weighted(b.z, d1 + 34u) ^ dim_weighted(b.w, d1 + 35u);

    // ---- butterfly XOR over each 8-lane group (3 steps, 4 tokens at once) ----
    r ^= __shfl_xor_sync(0xFFFFFFFFu, r, 4);
    r ^= __shfl_xor_sync(0xFFFFFFFFu, r, 2);
    r ^= __shfl_xor_sync(0xFFFFFFFFu, r, 1);

    const uint32_t base = r & 63u;          // hash-0 expert; hash-1 = base^1
    const uint32_t hit  = base >> 2;        // which float4 chunk holds the pair

    // ---- mask: lane owns chunks j and j+8; hit pair fills xy or zw ----
    const bool hiPair = (base & 2u) != 0u;
    const float lo = hiPair ? 0.0f : 0.5f;
    const float hi = hiPair ? 0.5f : 0.0f;
    const float4 hitv = make_float4(lo, lo, hi, hi);
    const float4 zero = make_float4(0.0f, 0.0f, 0.0f, 0.0f);
    const float4 m0 = (hit == j)      ? hitv : zero;
    const float4 m1 = (hit == j + 8u) ? hitv : zero;

    float4* mrow = out_mask + token * (N_EXPERTS / 4);
    mrow[j]      = m0;
    mrow[j + 8u] = m1;

    // ---- selected + weights: one lane per token, predicated stores ----
    if (j == 0u) {
        out_sel[token] = make_float2((float)base, (float)(base ^ 1u));
        out_w[token]   = make_float2(0.5f, 0.5f);
    }
}

extern "C" void kernel_launch(void* const* d_in, const int* in_sizes, int n_in,
                              void* d_out, int out_size)
{
    const float4* hs4 = (const float4*)d_in[0];
    int n_tokens = in_sizes[0] / HIDDEN_DIM;

    // Concat layout (verified): [selected (2N) | weights (2N) | masks (64N)].
    // Degenerate fallback: if out_size is smaller than expected, shrink N so
    // all stores stay in bounds (never triggered in practice).
    long long n = n_tokens;
    if ((long long)out_size < n * (2 * K_ACTIVE + N_EXPERTS)) {
        n = (long long)out_size / (2 * K_ACTIVE + N_EXPERTS);
        n_tokens = (int)n;
    }

    float* out = (float*)d_out;
    float2* out_sel  = (float2*)out;
    float2* out_w    = (float2*)(out + 2 * n);
    float4* out_mask = (float4*)(out + 4 * n);

    // 128 threads = 4 warps = 16 tokens per block
    const int blocks = (n_tokens + 15) / 16;
    multihash_router_kernel<<<blocks, 128>>>(hs4, out_sel, out_w, out_mask,
                                             n_tokens);
}

// round 9
// speedup vs baseline: 1.3949x; 1.0036x over previous
#include <cuda_runtime.h>
#include <cstdint>

// MultiHashRouter — latency/overhead-bound round.
// (Re-submit: prior two rounds were broker/container failures; removed the
//  large static __device__ scratch arrays as the only kernel-side suspect.)
//
// Math (LAYER_ID=0, SALT=0):
//   r = XOR_{d=0..63} dim_value[d]*(d+1);  expert_ids[h] = (r&63)^h (all distinct)
//   selected = [base, base^1], weights = 0.5
//   mask row: 0.5 at the aligned column pair {base&~1, base|1}.
//
// 4 tokens per warp: 8 lanes per token, each lane loads 2 float4 chunks
// (MLP=2), 3-step butterfly over 8 lanes, unconditional coalesced stores.
// Output layout (verified over two passing rounds):
//   [selected (2N) | weights (2N) | masks (64N)]  as float32.

#define HIDDEN_DIM 1024
#define N_EXPERTS  64
#define K_ACTIVE   2

__device__ __forceinline__ uint32_t dim_weighted(float h, uint32_t dplus1) {
    uint32_t u  = __float_as_uint(h);
    uint32_t au = u & 0x7fffffffu;                       // |h| bits; 0 iff h==±0
    uint32_t mag = (uint32_t)min((int)fabsf(h), 7);      // F2I(|h|) + IMNMX
    uint32_t code = ((u >> 28) & 8u) | 4u;               // 4 (pos) / 12 (neg)
    uint32_t dv = au ? (code | mag) : 0u;                // ±0 -> dim_value 0
    return dv * dplus1;
}

__global__ __launch_bounds__(128, 16)
void multihash_router_kernel(const float4* __restrict__ hs4,
                             float2* __restrict__ out_sel,   // [N]
                             float2* __restrict__ out_w,     // [N]
                             float4* __restrict__ out_mask,  // [N,16]
                             int n_tokens)
{
    const uint32_t lane = threadIdx.x & 31u;
    const uint32_t warp = threadIdx.x >> 5;
    const uint32_t tw   = lane >> 3;        // token within warp, 0..3
    const uint32_t j    = lane & 7u;        // chunk lane within token, 0..7
    const uint32_t token = (blockIdx.x * 4u + warp) * 4u + tw;
    if (token >= (uint32_t)n_tokens) return;

    // ---- two LDG.128 per lane, issued back-to-back (MLP=2) ----
    const float4* row = hs4 + token * (HIDDEN_DIM / 4);
    const float4 a = row[j];        // dims 4j .. 4j+3
    const float4 b = row[j + 8];    // dims 4j+32 .. 4j+35

    const uint32_t d1 = 4u * j + 1u;
    uint32_t r = dim_weighted(a.x, d1)       ^ dim_weighted(a.y, d1 + 1u)
               ^ dim_weighted(a.z, d1 + 2u)  ^ dim_weighted(a.w, d1 + 3u)
               ^ dim_weighted(b.x, d1 + 32u) ^ dim_weighted(b.y, d1 + 33u)
               ^ dim_weighted(b.z, d1 + 34u) ^ dim_weighted(b.w, d1 + 35u);

    // ---- butterfly XOR over each 8-lane group (3 steps, 4 tokens at once) ----
    r ^= __shfl_xor_sync(0xFFFFFFFFu, r, 4);
    r ^= __shfl_xor_sync(0xFFFFFFFFu, r, 2);
    r ^= __shfl_xor_sync(0xFFFFFFFFu, r, 1);

    const uint32_t base = r & 63u;          // hash-0 expert; hash-1 = base^1
    const uint32_t hit  = base >> 2;        // which float4 chunk holds the pair

    // ---- mask: lane owns chunks j and j+8; hit pair fills xy or zw ----
    const bool hiPair = (base & 2u) != 0u;
    const float lo = hiPair ? 0.0f : 0.5f;
    const float hi = hiPair ? 0.5f : 0.0f;
    const float4 hitv = make_float4(lo, lo, hi, hi);
    const float4 zero = make_float4(0.0f, 0.0f, 0.0f, 0.0f);
    const float4 m0 = (hit == j)      ? hitv : zero;
    const float4 m1 = (hit == j + 8u) ? hitv : zero;

    float4* mrow = out_mask + token * (N_EXPERTS / 4);
    mrow[j]      = m0;
    mrow[j + 8u] = m1;

    // ---- selected + weights: one lane per token, predicated stores ----
    if (j == 0u) {
        out_sel[token] = make_float2((float)base, (float)(base ^ 1u));
        out_w[token]   = make_float2(0.5f, 0.5f);
    }
}

extern "C" void kernel_launch(void* const* d_in, const int* in_sizes, int n_in,
                              void* d_out, int out_size)
{
    const float4* hs4 = (const float4*)d_in[0];
    int n_tokens = in_sizes[0] / HIDDEN_DIM;

    // Concat layout (verified): [selected (2N) | weights (2N) | masks (64N)].
    // Degenerate fallback: if out_size is smaller than expected, shrink N so
    // all stores stay in bounds (never triggered in practice).
    long long n = n_tokens;
    if ((long long)out_size < n * (2 * K_ACTIVE + N_EXPERTS)) {
        n = (long long)out_size / (2 * K_ACTIVE + N_EXPERTS);
        n_tokens = (int)n;
    }

    float* out = (float*)d_out;
    float2* out_sel  = (float2*)out;
    float2* out_w    = (float2*)(out + 2 * n);
    float4* out_mask = (float4*)(out + 4 * n);

    // 128 threads = 4 warps = 16 tokens per block
    const int blocks = (n_tokens + 15) / 16;
    multihash_router_kernel<<<blocks, 128>>>(hs4, out_sel, out_w, out_mask,
                                             n_tokens);
}

// round 10
// speedup vs baseline: 1.4259x; 1.0222x over previous
#include <cuda_runtime.h>
#include <cstdint>

// MultiHashRouter — single-wave / high-MLP round.
//
// Math (LAYER_ID=0, SALT=0):
//   r = XOR_{d=0..63} dim_value[d]*(d+1);  expert_ids[h] = (r&63)^h (distinct)
//   selected = [base, base^1], weights = 0.5
//   mask row: 0.5 at the aligned column pair {base&~1, base|1}.
//
// Layout: 8-lane groups (4 per warp), each group handles 4 tokens
// sequentially with all 8 LDG.128 front-batched (MLP=8 per lane).
// Warp covers 16 tokens, block (128 thr) covers 64 → grid 1024 = one wave.
// Output: [selected (2N) | weights (2N) | masks (64N)] float32 (verified).

#define HIDDEN_DIM 1024
#define N_EXPERTS  64
#define K_ACTIVE   2
#define TOK_ITER   4

__device__ __forceinline__ uint32_t dim_weighted(float h, uint32_t dplus1) {
    // dv = [h!=0] * ( (signbit<<3) | 4 | min(int(|h|),7) ), then * (d+1).
    uint32_t u = __float_as_uint(h);
    uint32_t mag = (uint32_t)(int)fminf(fabsf(h), 7.0f);   // FMNMX (fma pipe) + F2I
    uint32_t code = ((u >> 28) & 8u) | 4u;                  // SHF + LOP3
    uint32_t dv = (h != 0.0f) ? (code | mag) : 0u;          // FSETP + LOP3 + SEL
    return dv * dplus1;                                     // IMAD
}

__global__ __launch_bounds__(128)
void multihash_router_kernel(const float4* __restrict__ hs4,
                             float2* __restrict__ out_sel,   // [N]
                             float2* __restrict__ out_w,     // [N]
                             float4* __restrict__ out_mask,  // [N,16]
                             int n_tokens)
{
    const uint32_t lane = threadIdx.x & 31u;
    const uint32_t warp = threadIdx.x >> 5;
    const uint32_t g    = lane >> 3;          // lane-group 0..3
    const uint32_t j    = lane & 7u;          // chunk lane within group
    const uint32_t wb   = (blockIdx.x * 4u + warp) * 16u;   // warp's first token

    // ---- front-batched loads: 8 independent LDG.128 per lane ----
    float4 a[TOK_ITER], b[TOK_ITER];
    #pragma unroll
    for (int i = 0; i < TOK_ITER; i++) {
        uint32_t t = wb + 4u * i + g;
        uint32_t tc = min(t, (uint32_t)(n_tokens - 1));     // clamp (safe read)
        const float4* row = hs4 + (size_t)tc * (HIDDEN_DIM / 4);
        a[i] = row[j];          // dims 4j .. 4j+3
        b[i] = row[j + 8];      // dims 4j+32 .. 4j+35
    }

    const uint32_t d1 = 4u * j + 1u;
    const float4 zero = make_float4(0.0f, 0.0f, 0.0f, 0.0f);

    #pragma unroll
    for (int i = 0; i < TOK_ITER; i++) {
        uint32_t r = dim_weighted(a[i].x, d1)       ^ dim_weighted(a[i].y, d1 + 1u)
                   ^ dim_weighted(a[i].z, d1 + 2u)  ^ dim_weighted(a[i].w, d1 + 3u)
                   ^ dim_weighted(b[i].x, d1 + 32u) ^ dim_weighted(b[i].y, d1 + 33u)
                   ^ dim_weighted(b[i].z, d1 + 34u) ^ dim_weighted(b[i].w, d1 + 35u);

        // butterfly XOR over each 8-lane group (groups are independent tokens)
        r ^= __shfl_xor_sync(0xFFFFFFFFu, r, 4);
        r ^= __shfl_xor_sync(0xFFFFFFFFu, r, 2);
        r ^= __shfl_xor_sync(0xFFFFFFFFu, r, 1);

        const uint32_t base = r & 63u;        // hash-0 expert; hash-1 = base^1
        const uint32_t hit  = base >> 2;      // float4 chunk holding the pair

        const bool hiPair = (base & 2u) != 0u;
        const float lo = hiPair ? 0.0f : 0.5f;
        const float hi = hiPair ? 0.5f : 0.0f;
        const float4 hitv = make_float4(lo, lo, hi, hi);
        const float4 m0 = (hit == j)      ? hitv : zero;
        const float4 m1 = (hit == j + 8u) ? hitv : zero;

        const uint32_t t = wb + 4u * i + g;
        if (t < (uint32_t)n_tokens) {
            float4* mrow = out_mask + (size_t)t * (N_EXPERTS / 4);
            mrow[j]      = m0;
            mrow[j + 8u] = m1;
            if (j == 0u) {
                out_sel[t] = make_float2((float)base, (float)(base ^ 1u));
                out_w[t]   = make_float2(0.5f, 0.5f);
            }
        }
    }
}

extern "C" void kernel_launch(void* const* d_in, const int* in_sizes, int n_in,
                              void* d_out, int out_size)
{
    const float4* hs4 = (const float4*)d_in[0];
    int n_tokens = in_sizes[0] / HIDDEN_DIM;

    // Concat layout (verified): [selected (2N) | weights (2N) | masks (64N)].
    long long n = n_tokens;
    if ((long long)out_size < n * (2 * K_ACTIVE + N_EXPERTS)) {
        n = (long long)out_size / (2 * K_ACTIVE + N_EXPERTS);
        n_tokens = (int)n;
    }

    float* out = (float*)d_out;
    float2* out_sel  = (float2*)out;
    float2* out_w    = (float2*)(out + 2 * n);
    float4* out_mask = (float4*)(out + 4 * n);

    // 128 threads = 4 warps = 64 tokens per block
    const int blocks = (n_tokens + 63) / 64;
    multihash_router_kernel<<<blocks, 128>>>(hs4, out_sel, out_w, out_mask,
                                             n_tokens);
}